// round 2
// baseline (speedup 1.0000x reference)
#include <cuda_runtime.h>
#include <math.h>

#define NN 100000
#define DD 128
#define NE 800000
#define BM 64          // GEMM rows per CTA tile
#define HSTRIDE 132    // padded row stride (floats) for h tiles in smem

typedef unsigned long long ull;

// Scratch (allocations are banned; device globals are the sanctioned escape hatch)
__device__ float g_h[NN * DD];      // normalized features
__device__ float g_agg[NN * DD];    // edge-sum accumulator
__device__ float g_deg[NN];         // in-degree (float)
__device__ float g_sum[DD];
__device__ float g_sumsq[DD];

// ---------------------------------------------------------------------------
// packed f32x2 helpers (FFMA2 is only reachable via PTX fma.rn.f32x2)
__device__ __forceinline__ ull pack_dup(float a) {
    ull r;
    asm("mov.b64 %0, {%1, %1};" : "=l"(r) : "f"(a));
    return r;
}
__device__ __forceinline__ void fma2(ull& d, ull a, ull b) {
    asm("fma.rn.f32x2 %0, %1, %2, %0;" : "+l"(d) : "l"(a), "l"(b));
}
__device__ __forceinline__ ull add2(ull a, ull b) {
    ull r;
    asm("add.rn.f32x2 %0, %1, %2;" : "=l"(r) : "l"(a), "l"(b));
    return r;
}
__device__ __forceinline__ void unpack2(ull v, float& lo, float& hi) {
    asm("mov.b64 {%0, %1}, %2;" : "=f"(lo), "=f"(hi) : "l"(v));
}

// ---------------------------------------------------------------------------
// Zero the per-iteration accumulators (graph is replayed; must reset each call)
__global__ void k_zero() {
    int idx = blockIdx.x * blockDim.x + threadIdx.x;
    int stride = gridDim.x * blockDim.x;
    float4 z = make_float4(0.f, 0.f, 0.f, 0.f);
    float4* agg4 = reinterpret_cast<float4*>(g_agg);
    const int n4 = NN * DD / 4;
    for (int i = idx; i < n4; i += stride) agg4[i] = z;
    for (int i = idx; i < NN; i += stride) g_deg[i] = 0.f;
    if (idx < DD) { g_sum[idx] = 0.f; g_sumsq[idx] = 0.f; }
}

// ---------------------------------------------------------------------------
// Column sums / sum-of-squares
__global__ void k_stats(const float* __restrict__ feat) {
    int d = threadIdx.x;
    float s = 0.f, s2 = 0.f;
    for (int r = blockIdx.x; r < NN; r += gridDim.x) {
        float v = feat[r * DD + d];
        s += v;
        s2 += v * v;
    }
    atomicAdd(&g_sum[d], s);
    atomicAdd(&g_sumsq[d], s2);
}

// ---------------------------------------------------------------------------
// BatchNorm normalize: h = (x - mean) * rsqrt(var + eps) * gamma + beta
__global__ void k_norm(const float* __restrict__ feat,
                       const float* __restrict__ gamma,
                       const float* __restrict__ beta) {
    int d = threadIdx.x;
    const float invN = 1.f / (float)NN;
    float mean = g_sum[d] * invN;
    float var  = fmaxf(g_sumsq[d] * invN - mean * mean, 0.f);
    float isg  = rsqrtf(var + 1e-5f) * gamma[d];
    float be   = beta[d];
    for (int r = blockIdx.x; r < NN; r += gridDim.x)
        g_h[r * DD + d] = (feat[r * DD + d] - mean) * isg + be;
}

// ---------------------------------------------------------------------------
// Edge aggregation: one warp per edge; vector red.global, lane0 counts degree
__global__ void k_agg(const int* __restrict__ src, const int* __restrict__ dst) {
    int warp = (blockIdx.x * blockDim.x + threadIdx.x) >> 5;
    int lane = threadIdx.x & 31;
    if (warp >= NE) return;
    int s = src[warp];
    int t = dst[warp];
    const float4* hp = reinterpret_cast<const float4*>(g_h + (size_t)s * DD);
    float4 v = hp[lane];
    float* ap = g_agg + (size_t)t * DD + lane * 4;
    asm volatile("red.global.add.v4.f32 [%0], {%1, %2, %3, %4};"
                 :: "l"(ap), "f"(v.x), "f"(v.y), "f"(v.z), "f"(v.w)
                 : "memory");
    if (lane == 0) atomicAdd(&g_deg[t], 1.f);
}

// ---------------------------------------------------------------------------
// Fused dual-GEMM + bias + GELU using packed f32x2 FMA (2x FFMA throughput).
// Skip connection folded into W_self (+= Identity at staging time).
// Tile: 64 rows x 128 cols per CTA; thread = 4 rows x 8 cols x 2 matrices.
__device__ __forceinline__ float gelu_exact(float x) {
    return 0.5f * x * (1.f + erff(x * 0.70710678118654752f));
}

__global__ void __launch_bounds__(256, 1)
k_gemm(const float* __restrict__ Wself,
       const float* __restrict__ Wneigh,
       const float* __restrict__ bias,
       float* __restrict__ out) {
    extern __shared__ float sm[];
    float* Ws = sm;                        // 128*128  (W_self + I)
    float* Wn = Ws + DD * DD;              // 128*128
    float* HS = Wn + DD * DD;              // 64*132
    float* HN = HS + BM * HSTRIDE;         // 64*132
    float* IV = HN + BM * HSTRIDE;         // 64
    float* BS = IV + BM;                   // 128

    const int tid = threadIdx.x;           // 256 threads
    const int tx = tid & 15;               // cols tx*8 .. tx*8+7
    const int ty = tid >> 4;               // rows ty*4 .. ty*4+3

    // Stage weights + bias once per CTA
    {
        float4* Ws4 = reinterpret_cast<float4*>(Ws);
        float4* Wn4 = reinterpret_cast<float4*>(Wn);
        const float4* Wsg = reinterpret_cast<const float4*>(Wself);
        const float4* Wng = reinterpret_cast<const float4*>(Wneigh);
        const int nw4 = DD * DD / 4;
        for (int i = tid; i < nw4; i += 256) { Ws4[i] = Wsg[i]; Wn4[i] = Wng[i]; }
        if (tid < DD) BS[tid] = bias[tid];
    }
    __syncthreads();
    if (tid < DD) Ws[tid * DD + tid] += 1.0f;   // fold skip connection
    __syncthreads();

    const int ntiles = (NN + BM - 1) / BM;      // 1563 (last tile partial)
    const float4* hg = reinterpret_cast<const float4*>(g_h);
    const float4* ag = reinterpret_cast<const float4*>(g_agg);

    for (int tile = blockIdx.x; tile < ntiles; tile += gridDim.x) {
        const int row0 = tile * BM;

        __syncthreads();                    // protect smem from previous tile
        if (tid < BM) {
            int r = min(row0 + tid, NN - 1);
            IV[tid] = 1.f / fmaxf(g_deg[r], 1.f);
        }
        __syncthreads();

        // Load h-tile and (agg*inv_deg)-tile into padded smem
        float4* HS4 = reinterpret_cast<float4*>(HS);
        float4* HN4 = reinterpret_cast<float4*>(HN);
#pragma unroll
        for (int i = 0; i < 8; i++) {
            int e = tid + i * 256;              // 0..2047
            int row = e >> 5;                   // 0..63
            int c4  = e & 31;                   // float4 column index
            int gr  = min(row0 + row, NN - 1);
            float iv = IV[row];
            float4 hv = hg[(size_t)gr * 32 + c4];
            float4 av = ag[(size_t)gr * 32 + c4];
            HS4[row * (HSTRIDE / 4) + c4] = hv;
            HN4[row * (HSTRIDE / 4) + c4] =
                make_float4(av.x * iv, av.y * iv, av.z * iv, av.w * iv);
        }
        __syncthreads();

        ull acc_s[4][4], acc_n[4][4];
#pragma unroll
        for (int r = 0; r < 4; r++)
#pragma unroll
            for (int c = 0; c < 4; c++) { acc_s[r][c] = 0ull; acc_n[r][c] = 0ull; }

        const float* hsrow = HS + (ty * 4) * HSTRIDE;
        const float* hnrow = HN + (ty * 4) * HSTRIDE;

#pragma unroll 4
        for (int k = 0; k < DD; k++) {
            const ulonglong2* wsr = reinterpret_cast<const ulonglong2*>(Ws + k * DD);
            const ulonglong2* wnr = reinterpret_cast<const ulonglong2*>(Wn + k * DD);
            ulonglong2 s0 = wsr[2 * tx];
            ulonglong2 s1 = wsr[2 * tx + 1];
            ulonglong2 n0 = wnr[2 * tx];
            ulonglong2 n1 = wnr[2 * tx + 1];
#pragma unroll
            for (int r = 0; r < 4; r++) {
                ull a  = pack_dup(hsrow[r * HSTRIDE + k]);
                ull an = pack_dup(hnrow[r * HSTRIDE + k]);
                fma2(acc_s[r][0], a, s0.x);
                fma2(acc_s[r][1], a, s0.y);
                fma2(acc_s[r][2], a, s1.x);
                fma2(acc_s[r][3], a, s1.y);
                fma2(acc_n[r][0], an, n0.x);
                fma2(acc_n[r][1], an, n0.y);
                fma2(acc_n[r][2], an, n1.x);
                fma2(acc_n[r][3], an, n1.y);
            }
        }

        // Epilogue: combine, + bias, exact GELU, store (skip already in Ws)
#pragma unroll
        for (int r = 0; r < 4; r++) {
            int grow = row0 + ty * 4 + r;
            if (grow < NN) {
                float o[8];
#pragma unroll
                for (int c = 0; c < 4; c++) {
                    ull t = add2(acc_s[r][c], acc_n[r][c]);
                    float lo, hi;
                    unpack2(t, lo, hi);
                    o[2 * c]     = gelu_exact(lo + BS[tx * 8 + 2 * c]);
                    o[2 * c + 1] = gelu_exact(hi + BS[tx * 8 + 2 * c + 1]);
                }
                float4* op = reinterpret_cast<float4*>(out + (size_t)grow * DD + tx * 8);
                op[0] = make_float4(o[0], o[1], o[2], o[3]);
                op[1] = make_float4(o[4], o[5], o[6], o[7]);
            }
        }
    }
}

// ---------------------------------------------------------------------------
extern "C" void kernel_launch(void* const* d_in, const int* in_sizes, int n_in,
                              void* d_out, int out_size) {
    const float* features = (const float*)d_in[0];
    const int*   src      = (const int*)d_in[1];
    const int*   dst      = (const int*)d_in[2];
    const float* gamma    = (const float*)d_in[3];
    const float* beta     = (const float*)d_in[4];
    const float* W_self   = (const float*)d_in[5];
    const float* W_neigh  = (const float*)d_in[6];
    const float* b        = (const float*)d_in[7];
    float* out = (float*)d_out;

    const int GEMM_SMEM =
        (2 * DD * DD + 2 * BM * HSTRIDE + BM + DD) * (int)sizeof(float);
    cudaFuncSetAttribute(k_gemm, cudaFuncAttributeMaxDynamicSharedMemorySize, GEMM_SMEM);

    k_zero<<<1024, 256>>>();
    k_stats<<<512, 128>>>(features);
    k_norm<<<512, 128>>>(features, gamma, beta);
    k_agg<<<NE / 8, 256>>>(src, dst);
    k_gemm<<<148, 256, GEMM_SMEM>>>(W_self, W_neigh, b, out);
}

// round 3
// speedup vs baseline: 1.0063x; 1.0063x over previous
#include <cuda_runtime.h>
#include <math.h>

#define NN 100000
#define DD 128
#define NE 800000
#define BM 96          // GEMM rows per CTA tile
#define HSTRIDE 132    // padded row stride (floats) for h tiles in smem

typedef unsigned long long ull;

// Scratch (allocations are banned; device globals are the sanctioned escape hatch)
__device__ float g_h[NN * DD];      // normalized features
__device__ float g_agg[NN * DD];    // edge-sum accumulator
__device__ float g_deg[NN];         // in-degree (float)
__device__ float g_sum[DD];
__device__ float g_sumsq[DD];

// ---------------------------------------------------------------------------
// packed f32x2 helpers (FFMA2 only reachable via PTX fma.rn.f32x2)
__device__ __forceinline__ ull pack_dup(float a) {
    ull r;
    asm("mov.b64 %0, {%1, %1};" : "=l"(r) : "f"(a));
    return r;
}
__device__ __forceinline__ void fma2(ull& d, ull a, ull b) {
    asm("fma.rn.f32x2 %0, %1, %2, %0;" : "+l"(d) : "l"(a), "l"(b));
}
__device__ __forceinline__ ull add2(ull a, ull b) {
    ull r;
    asm("add.rn.f32x2 %0, %1, %2;" : "=l"(r) : "l"(a), "l"(b));
    return r;
}
__device__ __forceinline__ void unpack2(ull v, float& lo, float& hi) {
    asm("mov.b64 {%0, %1}, %2;" : "=f"(lo), "=f"(hi) : "l"(v));
}

// ---------------------------------------------------------------------------
__global__ void k_zero() {
    int idx = blockIdx.x * blockDim.x + threadIdx.x;
    int stride = gridDim.x * blockDim.x;
    float4 z = make_float4(0.f, 0.f, 0.f, 0.f);
    float4* agg4 = reinterpret_cast<float4*>(g_agg);
    const int n4 = NN * DD / 4;
    for (int i = idx; i < n4; i += stride) agg4[i] = z;
    for (int i = idx; i < NN; i += stride) g_deg[i] = 0.f;
    if (idx < DD) { g_sum[idx] = 0.f; g_sumsq[idx] = 0.f; }
}

// ---------------------------------------------------------------------------
__global__ void k_stats(const float* __restrict__ feat) {
    int d = threadIdx.x;
    float s = 0.f, s2 = 0.f;
    for (int r = blockIdx.x; r < NN; r += gridDim.x) {
        float v = feat[r * DD + d];
        s += v;
        s2 += v * v;
    }
    atomicAdd(&g_sum[d], s);
    atomicAdd(&g_sumsq[d], s2);
}

// ---------------------------------------------------------------------------
__global__ void k_norm(const float* __restrict__ feat,
                       const float* __restrict__ gamma,
                       const float* __restrict__ beta) {
    int d = threadIdx.x;
    const float invN = 1.f / (float)NN;
    float mean = g_sum[d] * invN;
    float var  = fmaxf(g_sumsq[d] * invN - mean * mean, 0.f);
    float isg  = rsqrtf(var + 1e-5f) * gamma[d];
    float be   = beta[d];
    for (int r = blockIdx.x; r < NN; r += gridDim.x)
        g_h[r * DD + d] = (feat[r * DD + d] - mean) * isg + be;
}

// ---------------------------------------------------------------------------
// Edge aggregation: one warp per edge; vector red.global, lane0 counts degree
__global__ void k_agg(const int* __restrict__ src, const int* __restrict__ dst) {
    int warp = (blockIdx.x * blockDim.x + threadIdx.x) >> 5;
    int lane = threadIdx.x & 31;
    if (warp >= NE) return;
    int s = src[warp];
    int t = dst[warp];
    const float4* hp = reinterpret_cast<const float4*>(g_h + (size_t)s * DD);
    float4 v = hp[lane];
    float* ap = g_agg + (size_t)t * DD + lane * 4;
    asm volatile("red.global.add.v4.f32 [%0], {%1, %2, %3, %4};"
                 :: "l"(ap), "f"(v.x), "f"(v.y), "f"(v.z), "f"(v.w)
                 : "memory");
    if (lane == 0) atomicAdd(&g_deg[t], 1.f);
}

// ---------------------------------------------------------------------------
// Fused dual-GEMM + bias + GELU. 6x8x2 micro-tile of packed f32x2 accumulators
// so the FFMA2 pipe (192 cyc/k/SM) dominates the smem crossbar (160 cyc/k/SM).
// Skip connection folded into W_self (+I). smem: 232448B = exactly the cap.
__device__ __forceinline__ float gelu_exact(float x) {
    return 0.5f * x * (1.f + erff(x * 0.70710678118654752f));
}

__global__ void __launch_bounds__(256, 1)
k_gemm(const float* __restrict__ Wself,
       const float* __restrict__ Wneigh,
       const float* __restrict__ bias,
       float* __restrict__ out) {
    extern __shared__ float sm[];
    float* Ws = sm;                        // 128*128 (W_self + I)
    float* Wn = Ws + DD * DD;              // 128*128
    float* HS = Wn + DD * DD;              // 96*132
    float* HN = HS + BM * HSTRIDE;         // 96*132

    const int tid = threadIdx.x;           // 256 threads
    const int tx = tid & 15;               // cols tx*8 .. tx*8+7
    const int ty = tid >> 4;               // rows ty*6 .. ty*6+5

    // Stage weights once per CTA
    {
        float4* Ws4 = reinterpret_cast<float4*>(Ws);
        float4* Wn4 = reinterpret_cast<float4*>(Wn);
        const float4* Wsg = reinterpret_cast<const float4*>(Wself);
        const float4* Wng = reinterpret_cast<const float4*>(Wneigh);
        const int nw4 = DD * DD / 4;
        for (int i = tid; i < nw4; i += 256) { Ws4[i] = Wsg[i]; Wn4[i] = Wng[i]; }
    }
    __syncthreads();
    if (tid < DD) Ws[tid * DD + tid] += 1.0f;   // fold skip connection
    __syncthreads();

    const int ntiles = (NN + BM - 1) / BM;      // 1042 (last tile = 64 rows)
    const float4* hg = reinterpret_cast<const float4*>(g_h);
    const float4* ag = reinterpret_cast<const float4*>(g_agg);

    for (int tile = blockIdx.x; tile < ntiles; tile += gridDim.x) {
        const int row0 = tile * BM;

        __syncthreads();                    // prior tile's k-loop readers done

        // Stage h-tile and (agg*inv_deg)-tile into padded smem
        float4* HS4 = reinterpret_cast<float4*>(HS);
        float4* HN4 = reinterpret_cast<float4*>(HN);
#pragma unroll
        for (int i = 0; i < 12; i++) {
            int e = tid + i * 256;              // 0..3071
            int row = e >> 5;                   // 0..95
            int c4  = e & 31;                   // float4 column index
            int gr  = min(row0 + row, NN - 1);
            float iv = 1.f / fmaxf(g_deg[gr], 1.f);
            float4 hv = hg[(size_t)gr * 32 + c4];
            float4 av = ag[(size_t)gr * 32 + c4];
            HS4[row * (HSTRIDE / 4) + c4] = hv;
            HN4[row * (HSTRIDE / 4) + c4] =
                make_float4(av.x * iv, av.y * iv, av.z * iv, av.w * iv);
        }
        __syncthreads();

        ull acc_s[6][4], acc_n[6][4];
#pragma unroll
        for (int r = 0; r < 6; r++)
#pragma unroll
            for (int c = 0; c < 4; c++) { acc_s[r][c] = 0ull; acc_n[r][c] = 0ull; }

        const float* hsrow = HS + (ty * 6) * HSTRIDE;
        const float* hnrow = HN + (ty * 6) * HSTRIDE;

#pragma unroll 4
        for (int k = 0; k < DD; k++) {
            const ulonglong2* wsr = reinterpret_cast<const ulonglong2*>(Ws + k * DD);
            const ulonglong2* wnr = reinterpret_cast<const ulonglong2*>(Wn + k * DD);
            ulonglong2 s0 = wsr[2 * tx];
            ulonglong2 s1 = wsr[2 * tx + 1];
            ulonglong2 n0 = wnr[2 * tx];
            ulonglong2 n1 = wnr[2 * tx + 1];
#pragma unroll
            for (int r = 0; r < 6; r++) {
                ull a  = pack_dup(hsrow[r * HSTRIDE + k]);
                ull an = pack_dup(hnrow[r * HSTRIDE + k]);
                fma2(acc_s[r][0], a, s0.x);
                fma2(acc_s[r][1], a, s0.y);
                fma2(acc_s[r][2], a, s1.x);
                fma2(acc_s[r][3], a, s1.y);
                fma2(acc_n[r][0], an, n0.x);
                fma2(acc_n[r][1], an, n0.y);
                fma2(acc_n[r][2], an, n1.x);
                fma2(acc_n[r][3], an, n1.y);
            }
        }

        // Epilogue: combine + bias + exact GELU (skip already folded into Ws)
        float4 b0 = reinterpret_cast<const float4*>(bias)[2 * tx];
        float4 b1 = reinterpret_cast<const float4*>(bias)[2 * tx + 1];
        float bv[8] = {b0.x, b0.y, b0.z, b0.w, b1.x, b1.y, b1.z, b1.w};
#pragma unroll
        for (int r = 0; r < 6; r++) {
            int grow = row0 + ty * 6 + r;
            if (grow < NN) {
                float o[8];
#pragma unroll
                for (int c = 0; c < 4; c++) {
                    ull t = add2(acc_s[r][c], acc_n[r][c]);
                    float lo, hi;
                    unpack2(t, lo, hi);
                    o[2 * c]     = gelu_exact(lo + bv[2 * c]);
                    o[2 * c + 1] = gelu_exact(hi + bv[2 * c + 1]);
                }
                float4* op = reinterpret_cast<float4*>(out + (size_t)grow * DD + tx * 8);
                op[0] = make_float4(o[0], o[1], o[2], o[3]);
                op[1] = make_float4(o[4], o[5], o[6], o[7]);
            }
        }
    }
}

// ---------------------------------------------------------------------------
extern "C" void kernel_launch(void* const* d_in, const int* in_sizes, int n_in,
                              void* d_out, int out_size) {
    const float* features = (const float*)d_in[0];
    const int*   src      = (const int*)d_in[1];
    const int*   dst      = (const int*)d_in[2];
    const float* gamma    = (const float*)d_in[3];
    const float* beta     = (const float*)d_in[4];
    const float* W_self   = (const float*)d_in[5];
    const float* W_neigh  = (const float*)d_in[6];
    const float* b        = (const float*)d_in[7];
    float* out = (float*)d_out;

    // 2*128*128 + 2*96*132 floats = 232448 bytes (exactly the 227KB opt-in cap)
    const int GEMM_SMEM = (2 * DD * DD + 2 * BM * HSTRIDE) * (int)sizeof(float);
    cudaFuncSetAttribute(k_gemm, cudaFuncAttributeMaxDynamicSharedMemorySize, GEMM_SMEM);

    k_zero<<<1024, 256>>>();
    k_stats<<<512, 128>>>(features);
    k_norm<<<512, 128>>>(features, gamma, beta);
    k_agg<<<NE / 8, 256>>>(src, dst);
    k_gemm<<<148, 256, GEMM_SMEM>>>(W_self, W_neigh, b, out);
}

// round 5
// speedup vs baseline: 1.1451x; 1.1379x over previous
#include <cuda_runtime.h>
#include <cuda_bf16.h>
#include <math.h>
#include <stdint.h>

#define NN 100000
#define DD 128
#define NE 800000
#define KK 256                      // concatenated K (h | h_neigh)
#define BMT 64                      // GEMM tile rows per CTA iteration
#define NTILES ((NN + BMT - 1) / BMT)   // 1563
#define KPAD 264                    // padded K stride (bf16 elems) for smem tiles

// ---------------------------------------------------------------------------
// device-global scratch (allocations banned)
__device__ float g_h[NN * DD];
__device__ float g_agg[NN * DD];
__device__ float g_deg[NN];
__device__ float g_sum[DD];
__device__ float g_sumsq[DD];
__device__ __nv_bfloat16 g_ahi[(size_t)NN * KK];   // A hi plane [row][k]
__device__ __nv_bfloat16 g_alo[(size_t)NN * KK];   // A lo plane [row][k]

// ---------------------------------------------------------------------------
__device__ __forceinline__ uint32_t smem_to_u32(const void* p) {
    uint32_t a;
    asm("{ .reg .u64 t; cvta.to.shared.u64 t, %1; cvt.u32.u64 %0, t; }"
        : "=r"(a) : "l"(p));
    return a;
}

#define LDSM_X4(r, addr) \
    asm volatile("ldmatrix.sync.aligned.m8n8.x4.shared.b16 {%0,%1,%2,%3}, [%4];" \
        : "=r"((r)[0]), "=r"((r)[1]), "=r"((r)[2]), "=r"((r)[3]) : "r"(addr))

#define MMA16816(c, a, b0, b1) \
    asm volatile("mma.sync.aligned.m16n8k16.row.col.f32.bf16.bf16.f32 " \
        "{%0,%1,%2,%3}, {%4,%5,%6,%7}, {%8,%9}, {%0,%1,%2,%3};" \
        : "+f"((c)[0]), "+f"((c)[1]), "+f"((c)[2]), "+f"((c)[3]) \
        : "r"((a)[0]), "r"((a)[1]), "r"((a)[2]), "r"((a)[3]), "r"(b0), "r"(b1))

// ---------------------------------------------------------------------------
__global__ void k_zero() {
    int idx = blockIdx.x * blockDim.x + threadIdx.x;
    int stride = gridDim.x * blockDim.x;
    float4 z = make_float4(0.f, 0.f, 0.f, 0.f);
    float4* agg4 = reinterpret_cast<float4*>(g_agg);
    const int n4 = NN * DD / 4;
    for (int i = idx; i < n4; i += stride) agg4[i] = z;
    for (int i = idx; i < NN; i += stride) g_deg[i] = 0.f;
    if (idx < DD) { g_sum[idx] = 0.f; g_sumsq[idx] = 0.f; }
}

__global__ void k_stats(const float* __restrict__ feat) {
    int d = threadIdx.x;
    float s = 0.f, s2 = 0.f;
    for (int r = blockIdx.x; r < NN; r += gridDim.x) {
        float v = feat[r * DD + d];
        s += v; s2 += v * v;
    }
    atomicAdd(&g_sum[d], s);
    atomicAdd(&g_sumsq[d], s2);
}

// normalize + write fp32 h (for aggregation) + bf16 hi/lo planes (GEMM A cols 0..127)
__global__ void k_norm(const float* __restrict__ feat,
                       const float* __restrict__ gamma,
                       const float* __restrict__ beta) {
    int d = threadIdx.x;
    const float invN = 1.f / (float)NN;
    float mean = g_sum[d] * invN;
    float var  = fmaxf(g_sumsq[d] * invN - mean * mean, 0.f);
    float isg  = rsqrtf(var + 1e-5f) * gamma[d];
    float be   = beta[d];
    for (int r = blockIdx.x; r < NN; r += gridDim.x) {
        float h = (feat[r * DD + d] - mean) * isg + be;
        g_h[r * DD + d] = h;
        __nv_bfloat16 hi = __float2bfloat16(h);
        g_ahi[(size_t)r * KK + d] = hi;
        g_alo[(size_t)r * KK + d] = __float2bfloat16(h - __bfloat162float(hi));
    }
}

__global__ void k_agg(const int* __restrict__ src, const int* __restrict__ dst) {
    int warp = (blockIdx.x * blockDim.x + threadIdx.x) >> 5;
    int lane = threadIdx.x & 31;
    if (warp >= NE) return;
    int s = src[warp];
    int t = dst[warp];
    const float4* hp = reinterpret_cast<const float4*>(g_h + (size_t)s * DD);
    float4 v = hp[lane];
    float* ap = g_agg + (size_t)t * DD + lane * 4;
    asm volatile("red.global.add.v4.f32 [%0], {%1, %2, %3, %4};"
                 :: "l"(ap), "f"(v.x), "f"(v.y), "f"(v.z), "f"(v.w)
                 : "memory");
    if (lane == 0) atomicAdd(&g_deg[t], 1.f);
}

// h_neigh = agg / max(deg,1) -> bf16 hi/lo planes, GEMM A cols 128..255
__global__ void k_div() {
    int d = threadIdx.x;
    for (int r = blockIdx.x; r < NN; r += gridDim.x) {
        float iv = 1.f / fmaxf(g_deg[r], 1.f);
        float hn = g_agg[r * DD + d] * iv;
        __nv_bfloat16 hi = __float2bfloat16(hn);
        g_ahi[(size_t)r * KK + DD + d] = hi;
        g_alo[(size_t)r * KK + DD + d] = __float2bfloat16(hn - __bfloat162float(hi));
    }
}

// ---------------------------------------------------------------------------
// bf16x3 tensor-core GEMM via mma.sync (plain compute_103-compatible PTX).
// D[64x128] = A[64x256] @ B_nk^T, B_nk[n][k] = W[k][n] (+I for k==n), then
// bias + exact GELU. B hi/lo planes resident in smem; A tile streamed.
__device__ __forceinline__ float gelu_exact(float x) {
    return 0.5f * x * (1.f + erff(x * 0.70710678118654752f));
}

// smem byte offsets
#define SM_BHI  0                                   // 128 x KPAD bf16 = 67584
#define SM_BLO  (SM_BHI + DD * KPAD * 2)            // 67584
#define SM_A    (SM_BLO + DD * KPAD * 2)            // A hi: 64xKPAD, A lo after
#define SM_ALO  (SM_A + BMT * KPAD * 2)
#define SM_BIAS (SM_ALO + BMT * KPAD * 2)           // 128 floats
#define SM_TOT  (SM_BIAS + 512)                     // 203776 B

__global__ void __launch_bounds__(256, 1)
k_gemm_mma(const float* __restrict__ Wself,
           const float* __restrict__ Wneigh,
           const float* __restrict__ bias,
           float* __restrict__ out) {
    extern __shared__ char smem[];
    const uint32_t smem_base = smem_to_u32(smem);
    const int tid  = threadIdx.x;
    const int wid  = tid >> 5;
    const int lane = tid & 31;

    // ---- stage B (once per CTA): coalesced W reads, transposed smem writes,
    // fold +I, split bf16 hi/lo.  B_nk[n][k] at (n*KPAD + k)*2 bytes.
    for (int i = 0; i < 32; i++) {
        int e = tid + i * 256;              // 0..8191 float4s
        int k = e >> 5;                     // 0..255 (K row)
        int c4 = e & 31;                    // float4 within the 128-wide row
        const float4* wr = (k < DD)
            ? reinterpret_cast<const float4*>(Wself  + (size_t)k * DD)
            : reinterpret_cast<const float4*>(Wneigh + (size_t)(k - DD) * DD);
        float4 w = wr[c4];
        float wv[4] = {w.x, w.y, w.z, w.w};
#pragma unroll
        for (int j = 0; j < 4; j++) {
            int n = c4 * 4 + j;
            float v = wv[j] + ((k < DD && n == k) ? 1.0f : 0.0f);
            __nv_bfloat16 hi = __float2bfloat16(v);
            __nv_bfloat16 lo = __float2bfloat16(v - __bfloat162float(hi));
            uint32_t off = ((uint32_t)n * KPAD + (uint32_t)k) * 2u;
            *reinterpret_cast<__nv_bfloat16*>(smem + SM_BHI + off) = hi;
            *reinterpret_cast<__nv_bfloat16*>(smem + SM_BLO + off) = lo;
        }
    }
    if (tid < DD) *reinterpret_cast<float*>(smem + SM_BIAS + tid * 4) = bias[tid];
    __syncthreads();

    const float* bias_s = reinterpret_cast<const float*>(smem + SM_BIAS);
    float* ob = reinterpret_cast<float*>(smem + SM_A);  // out staging reuses A

    const int wr = wid >> 2;                // warp row group: rows wr*32..+31
    const int wc = wid & 3;                 // warp col group: cols wc*32..+31

    // ldmatrix lane-address components (constant per thread)
    const int a_row_l = lane & 15;          // + (lane>>4)*8 in k
    const int a_k_l   = (lane >> 4) << 3;
    const int b_n_l   = ((lane >> 4) << 3) + (lane & 7);
    const int b_k_l   = ((lane >> 3) & 1) << 3;

    for (int tile = blockIdx.x; tile < NTILES; tile += gridDim.x) {
        const int row0 = tile * BMT;

        __syncthreads();                    // out-staging readers of prev tile done

        // ---- stage A tile (both planes) into padded smem
        for (int i = 0; i < 16; i++) {
            int e = tid + i * 256;          // 0..4095 uint4s
            int plane = e >> 11;            // 0: hi, 1: lo
            int r  = (e >> 5) & 63;
            int c4 = e & 31;                // 16B unit (8 bf16)
            int gr = min(row0 + r, NN - 1);
            const uint4* sp = plane
                ? reinterpret_cast<const uint4*>(g_alo + (size_t)gr * KK)
                : reinterpret_cast<const uint4*>(g_ahi + (size_t)gr * KK);
            uint4 v = sp[c4];
            *reinterpret_cast<uint4*>(smem + SM_A + plane * (BMT * KPAD * 2)
                                      + (r * KPAD + c4 * 8) * 2) = v;
        }
        __syncthreads();

        float c[2][4][4];
#pragma unroll
        for (int mt = 0; mt < 2; mt++)
#pragma unroll
            for (int nt = 0; nt < 4; nt++)
#pragma unroll
                for (int q = 0; q < 4; q++) c[mt][nt][q] = 0.f;

#pragma unroll 4
        for (int ks = 0; ks < 16; ks++) {
            const int k0 = ks * 16;
            uint32_t a_hi[2][4], a_lo[2][4], b_hi[2][4], b_lo[2][4];
#pragma unroll
            for (int mt = 0; mt < 2; mt++) {
                uint32_t ao = (uint32_t)((wr * 32 + mt * 16 + a_row_l) * KPAD
                                         + k0 + a_k_l) * 2u;
                LDSM_X4(a_hi[mt], smem_base + SM_A + ao);
                LDSM_X4(a_lo[mt], smem_base + SM_ALO + ao);
            }
#pragma unroll
            for (int g = 0; g < 2; g++) {
                uint32_t bo = (uint32_t)((wc * 32 + g * 16 + b_n_l) * KPAD
                                         + k0 + b_k_l) * 2u;
                LDSM_X4(b_hi[g], smem_base + SM_BHI + bo);
                LDSM_X4(b_lo[g], smem_base + SM_BLO + bo);
            }
#pragma unroll
            for (int mt = 0; mt < 2; mt++)
#pragma unroll
                for (int nt = 0; nt < 4; nt++) {
                    int g = nt >> 1, s = (nt & 1) * 2;
                    MMA16816(c[mt][nt], a_hi[mt], b_hi[g][s], b_hi[g][s + 1]);
                    MMA16816(c[mt][nt], a_hi[mt], b_lo[g][s], b_lo[g][s + 1]);
                    MMA16816(c[mt][nt], a_lo[mt], b_hi[g][s], b_hi[g][s + 1]);
                }
        }
        __syncthreads();                    // A reads done; reuse region for out

        // ---- stage accumulators to smem (stride 132 floats)
#pragma unroll
        for (int mt = 0; mt < 2; mt++)
#pragma unroll
            for (int nt = 0; nt < 4; nt++) {
                int row = wr * 32 + mt * 16 + (lane >> 2);
                int col = wc * 32 + nt * 8 + 2 * (lane & 3);
                ob[row * 132 + col]       = c[mt][nt][0];
                ob[row * 132 + col + 1]   = c[mt][nt][1];
                ob[(row + 8) * 132 + col]     = c[mt][nt][2];
                ob[(row + 8) * 132 + col + 1] = c[mt][nt][3];
            }
        __syncthreads();

        // ---- coalesced bias + GELU + store
#pragma unroll 4
        for (int i = 0; i < 32; i++) {
            int e = tid + i * 256;          // 0..8191
            int row = e >> 7;
            int col = e & 127;
            int grow = row0 + row;
            if (grow < NN) {
                float v = ob[row * 132 + col] + bias_s[col];
                out[(size_t)grow * DD + col] = gelu_exact(v);
            }
        }
    }
}

// ---------------------------------------------------------------------------
extern "C" void kernel_launch(void* const* d_in, const int* in_sizes, int n_in,
                              void* d_out, int out_size) {
    const float* features = (const float*)d_in[0];
    const int*   src      = (const int*)d_in[1];
    const int*   dst      = (const int*)d_in[2];
    const float* gamma    = (const float*)d_in[3];
    const float* beta     = (const float*)d_in[4];
    const float* W_self   = (const float*)d_in[5];
    const float* W_neigh  = (const float*)d_in[6];
    const float* b        = (const float*)d_in[7];
    float* out = (float*)d_out;

    cudaFuncSetAttribute(k_gemm_mma, cudaFuncAttributeMaxDynamicSharedMemorySize, SM_TOT);

    k_zero<<<1024, 256>>>();
    k_stats<<<512, 128>>>(features);
    k_norm<<<1024, 128>>>(features, gamma, beta);
    k_agg<<<NE / 8, 256>>>(src, dst);
    k_div<<<1024, 128>>>();
    k_gemm_mma<<<148, 256, SM_TOT>>>(W_self, W_neigh, b, out);
}

// round 6
// speedup vs baseline: 1.5589x; 1.3613x over previous
#include <cuda_runtime.h>
#include <cuda_bf16.h>
#include <math.h>
#include <stdint.h>

#define NN 100000
#define DD 128
#define NE 800000
#define KK 256                      // concatenated K (h | h_neigh)
#define BMT 64                      // GEMM tile rows per CTA iteration
#define NTILES ((NN + BMT - 1) / BMT)   // 1563
#define KPAD 264                    // padded K stride (bf16 elems) for smem tiles
#define NBLK 98                     // scan blocks: ceil(NN/1024)

// ---------------------------------------------------------------------------
// device-global scratch (allocations banned)
__device__ float g_h[NN * DD];      // normalized features (fp32)
__device__ float g_agg[NN * DD];    // h_neigh (mean-aggregated), written by gather
__device__ float g_sum[DD];
__device__ float g_sumsq[DD];
__device__ int   g_cnt[NN];         // in-degree counts
__device__ int   g_ptr[NN + 1];     // CSR row offsets
__device__ int   g_cur[NN];         // scatter cursors
__device__ int   g_csrc[NE];        // edge src ids grouped by dst
__device__ int   g_bsum[NBLK];      // scan block sums

// ---------------------------------------------------------------------------
__device__ __forceinline__ uint32_t smem_to_u32(const void* p) {
    uint32_t a;
    asm("{ .reg .u64 t; cvta.to.shared.u64 t, %1; cvt.u32.u64 %0, t; }"
        : "=r"(a) : "l"(p));
    return a;
}

#define LDSM_X4(r, addr) \
    asm volatile("ldmatrix.sync.aligned.m8n8.x4.shared.b16 {%0,%1,%2,%3}, [%4];" \
        : "=r"((r)[0]), "=r"((r)[1]), "=r"((r)[2]), "=r"((r)[3]) : "r"(addr))

#define MMA16816(c, a, b0, b1) \
    asm volatile("mma.sync.aligned.m16n8k16.row.col.f32.bf16.bf16.f32 " \
        "{%0,%1,%2,%3}, {%4,%5,%6,%7}, {%8,%9}, {%0,%1,%2,%3};" \
        : "+f"((c)[0]), "+f"((c)[1]), "+f"((c)[2]), "+f"((c)[3]) \
        : "r"((a)[0]), "r"((a)[1]), "r"((a)[2]), "r"((a)[3]), "r"(b0), "r"(b1))

// ---------------------------------------------------------------------------
// prep: zero counters + stats accumulators (nothing big anymore)
__global__ void k_prep() {
    int i = blockIdx.x * blockDim.x + threadIdx.x;
    int stride = gridDim.x * blockDim.x;
    for (int j = i; j < NN; j += stride) g_cnt[j] = 0;
    if (i < DD) { g_sum[i] = 0.f; g_sumsq[i] = 0.f; }
}

__global__ void k_count(const int* __restrict__ dst) {
    int i = blockIdx.x * blockDim.x + threadIdx.x;
    if (i < NE) atomicAdd(&g_cnt[dst[i]], 1);
}

__global__ void k_stats(const float* __restrict__ feat) {
    int d = threadIdx.x;
    float s = 0.f, s2 = 0.f;
    for (int r = blockIdx.x; r < NN; r += gridDim.x) {
        float v = feat[r * DD + d];
        s += v; s2 += v * v;
    }
    atomicAdd(&g_sum[d], s);
    atomicAdd(&g_sumsq[d], s2);
}

// ---- 2-level exclusive scan over g_cnt -> g_ptr --------------------------
__global__ void k_scan1() {
    __shared__ int s[1024];
    int tid = threadIdx.x;
    int i = blockIdx.x * 1024 + tid;
    int v = (i < NN) ? g_cnt[i] : 0;
    s[tid] = v;
    __syncthreads();
#pragma unroll
    for (int off = 1; off < 1024; off <<= 1) {
        int t = (tid >= off) ? s[tid - off] : 0;
        __syncthreads();
        s[tid] += t;
        __syncthreads();
    }
    if (i < NN) g_ptr[i] = s[tid] - v;          // exclusive
    if (tid == 1023) g_bsum[blockIdx.x] = s[1023];
}

__global__ void k_scan2() {
    __shared__ int s[128];
    int tid = threadIdx.x;
    int v = (tid < NBLK) ? g_bsum[tid] : 0;
    s[tid] = v;
    __syncthreads();
#pragma unroll
    for (int off = 1; off < 128; off <<= 1) {
        int t = (tid >= off) ? s[tid - off] : 0;
        __syncthreads();
        s[tid] += t;
        __syncthreads();
    }
    if (tid < NBLK) g_bsum[tid] = s[tid] - v;   // exclusive
}

__global__ void k_scan3() {
    int i = blockIdx.x * blockDim.x + threadIdx.x;
    if (i < NN) {
        int p = g_ptr[i] + g_bsum[i >> 10];
        g_ptr[i] = p;
        g_cur[i] = p;
    }
    if (i == 0) g_ptr[NN] = NE;
}

__global__ void k_scatter(const int* __restrict__ src, const int* __restrict__ dst) {
    int i = blockIdx.x * blockDim.x + threadIdx.x;
    if (i < NE) {
        int pos = atomicAdd(&g_cur[dst[i]], 1);
        g_csrc[pos] = src[i];
    }
}

// ---------------------------------------------------------------------------
// normalize: h = (x - mean) * rsqrt(var + eps) * gamma + beta  (fp32 only)
__global__ void k_norm(const float* __restrict__ feat,
                       const float* __restrict__ gamma,
                       const float* __restrict__ beta) {
    int d = threadIdx.x;
    const float invN = 1.f / (float)NN;
    float mean = g_sum[d] * invN;
    float var  = fmaxf(g_sumsq[d] * invN - mean * mean, 0.f);
    float isg  = rsqrtf(var + 1e-5f) * gamma[d];
    float be   = beta[d];
    for (int r = blockIdx.x; r < NN; r += gridDim.x)
        g_h[r * DD + d] = (feat[r * DD + d] - mean) * isg + be;
}

// ---------------------------------------------------------------------------
// gather-aggregate: one warp per dst node, pure reads, no atomics.
// h_neigh = mean of neighbor h rows (0 for zero-degree nodes).
__global__ void k_gather() {
    int gw = (blockIdx.x * blockDim.x + threadIdx.x) >> 5;
    int lane = threadIdx.x & 31;
    if (gw >= NN) return;
    int beg = g_ptr[gw];
    int end = g_ptr[gw + 1];
    float4 acc = make_float4(0.f, 0.f, 0.f, 0.f);
    for (int e = beg; e < end; e++) {
        int s = g_csrc[e];
        float4 v = reinterpret_cast<const float4*>(g_h + (size_t)s * DD)[lane];
        acc.x += v.x; acc.y += v.y; acc.z += v.z; acc.w += v.w;
    }
    float iv = 1.f / fmaxf((float)(end - beg), 1.f);
    reinterpret_cast<float4*>(g_agg + (size_t)gw * DD)[lane] =
        make_float4(acc.x * iv, acc.y * iv, acc.z * iv, acc.w * iv);
}

// ---------------------------------------------------------------------------
// bf16x3 tensor-core GEMM via mma.sync. A staged from fp32 g_h/g_agg with
// in-register hi/lo bf16 split. B_nk[n][k] = W[k][n] (+I), resident in smem.
__device__ __forceinline__ float gelu_exact(float x) {
    return 0.5f * x * (1.f + erff(x * 0.70710678118654752f));
}
__device__ __forceinline__ uint32_t pack_bf16x2(__nv_bfloat16 lo, __nv_bfloat16 hi) {
    __nv_bfloat162 p(lo, hi);
    return *reinterpret_cast<uint32_t*>(&p);
}

// smem byte offsets
#define SM_BHI  0                                   // 128 x KPAD bf16 = 67584
#define SM_BLO  (SM_BHI + DD * KPAD * 2)
#define SM_A    (SM_BLO + DD * KPAD * 2)            // A hi: 64xKPAD, A lo after
#define SM_ALO  (SM_A + BMT * KPAD * 2)
#define SM_BIAS (SM_ALO + BMT * KPAD * 2)           // 128 floats
#define SM_TOT  (SM_BIAS + 512)

__global__ void __launch_bounds__(256, 1)
k_gemm_mma(const float* __restrict__ Wself,
           const float* __restrict__ Wneigh,
           const float* __restrict__ bias,
           float* __restrict__ out) {
    extern __shared__ char smem[];
    const uint32_t smem_base = smem_to_u32(smem);
    const int tid  = threadIdx.x;
    const int wid  = tid >> 5;
    const int lane = tid & 31;

    // ---- stage B once: coalesced W reads, transposed writes, +I, hi/lo split
    for (int i = 0; i < 32; i++) {
        int e = tid + i * 256;              // 0..8191 float4s
        int k = e >> 5;                     // 0..255
        int c4 = e & 31;
        const float4* wr = (k < DD)
            ? reinterpret_cast<const float4*>(Wself  + (size_t)k * DD)
            : reinterpret_cast<const float4*>(Wneigh + (size_t)(k - DD) * DD);
        float4 w = wr[c4];
        float wv[4] = {w.x, w.y, w.z, w.w};
#pragma unroll
        for (int j = 0; j < 4; j++) {
            int n = c4 * 4 + j;
            float v = wv[j] + ((k < DD && n == k) ? 1.0f : 0.0f);
            __nv_bfloat16 hi = __float2bfloat16(v);
            __nv_bfloat16 lo = __float2bfloat16(v - __bfloat162float(hi));
            uint32_t off = ((uint32_t)n * KPAD + (uint32_t)k) * 2u;
            *reinterpret_cast<__nv_bfloat16*>(smem + SM_BHI + off) = hi;
            *reinterpret_cast<__nv_bfloat16*>(smem + SM_BLO + off) = lo;
        }
    }
    if (tid < DD) *reinterpret_cast<float*>(smem + SM_BIAS + tid * 4) = bias[tid];
    __syncthreads();

    const float* bias_s = reinterpret_cast<const float*>(smem + SM_BIAS);
    float* ob = reinterpret_cast<float*>(smem + SM_A);  // out staging reuses A

    const int wr2 = wid >> 2;               // warp row group
    const int wc  = wid & 3;                // warp col group

    const int a_row_l = lane & 15;
    const int a_k_l   = (lane >> 4) << 3;
    const int b_n_l   = ((lane >> 4) << 3) + (lane & 7);
    const int b_k_l   = ((lane >> 3) & 1) << 3;

    for (int tile = blockIdx.x; tile < NTILES; tile += gridDim.x) {
        const int row0 = tile * BMT;

        __syncthreads();                    // out-staging readers of prev tile done

        // ---- stage A tile: fp32 -> bf16 hi/lo split in registers
        for (int i = 0; i < 16; i++) {
            int e = tid + i * 256;          // 0..4095 float4s
            int r  = e >> 6;                // 0..63
            int c4 = e & 63;                // float4 col (k = c4*4)
            int gr = min(row0 + r, NN - 1);
            float4 v = (c4 < 32)
                ? reinterpret_cast<const float4*>(g_h   + (size_t)gr * DD)[c4]
                : reinterpret_cast<const float4*>(g_agg + (size_t)gr * DD)[c4 - 32];
            float x[4] = {v.x, v.y, v.z, v.w};
            __nv_bfloat16 h[4], l[4];
#pragma unroll
            for (int j = 0; j < 4; j++) {
                h[j] = __float2bfloat16(x[j]);
                l[j] = __float2bfloat16(x[j] - __bfloat162float(h[j]));
            }
            uint32_t boff = ((uint32_t)r * KPAD + (uint32_t)c4 * 4) * 2u;
            uint2 hv = make_uint2(pack_bf16x2(h[0], h[1]), pack_bf16x2(h[2], h[3]));
            uint2 lv = make_uint2(pack_bf16x2(l[0], l[1]), pack_bf16x2(l[2], l[3]));
            *reinterpret_cast<uint2*>(smem + SM_A   + boff) = hv;
            *reinterpret_cast<uint2*>(smem + SM_ALO + boff) = lv;
        }
        __syncthreads();

        float c[2][4][4];
#pragma unroll
        for (int mt = 0; mt < 2; mt++)
#pragma unroll
            for (int nt = 0; nt < 4; nt++)
#pragma unroll
                for (int q = 0; q < 4; q++) c[mt][nt][q] = 0.f;

#pragma unroll 4
        for (int ks = 0; ks < 16; ks++) {
            const int k0 = ks * 16;
            uint32_t a_hi[2][4], a_lo[2][4], b_hi[2][4], b_lo[2][4];
#pragma unroll
            for (int mt = 0; mt < 2; mt++) {
                uint32_t ao = (uint32_t)((wr2 * 32 + mt * 16 + a_row_l) * KPAD
                                         + k0 + a_k_l) * 2u;
                LDSM_X4(a_hi[mt], smem_base + SM_A + ao);
                LDSM_X4(a_lo[mt], smem_base + SM_ALO + ao);
            }
#pragma unroll
            for (int g = 0; g < 2; g++) {
                uint32_t bo = (uint32_t)((wc * 32 + g * 16 + b_n_l) * KPAD
                                         + k0 + b_k_l) * 2u;
                LDSM_X4(b_hi[g], smem_base + SM_BHI + bo);
                LDSM_X4(b_lo[g], smem_base + SM_BLO + bo);
            }
#pragma unroll
            for (int mt = 0; mt < 2; mt++)
#pragma unroll
                for (int nt = 0; nt < 4; nt++) {
                    int g = nt >> 1, s = (nt & 1) * 2;
                    MMA16816(c[mt][nt], a_hi[mt], b_hi[g][s], b_hi[g][s + 1]);
                    MMA16816(c[mt][nt], a_hi[mt], b_lo[g][s], b_lo[g][s + 1]);
                    MMA16816(c[mt][nt], a_lo[mt], b_hi[g][s], b_hi[g][s + 1]);
                }
        }
        __syncthreads();                    // A reads done; reuse region for out

        // ---- stage accumulators to smem (stride 132 floats)
#pragma unroll
        for (int mt = 0; mt < 2; mt++)
#pragma unroll
            for (int nt = 0; nt < 4; nt++) {
                int row = wr2 * 32 + mt * 16 + (lane >> 2);
                int col = wc * 32 + nt * 8 + 2 * (lane & 3);
                ob[row * 132 + col]           = c[mt][nt][0];
                ob[row * 132 + col + 1]       = c[mt][nt][1];
                ob[(row + 8) * 132 + col]     = c[mt][nt][2];
                ob[(row + 8) * 132 + col + 1] = c[mt][nt][3];
            }
        __syncthreads();

        // ---- coalesced bias + GELU + store
#pragma unroll 4
        for (int i = 0; i < 32; i++) {
            int e = tid + i * 256;
            int row = e >> 7;
            int col = e & 127;
            int grow = row0 + row;
            if (grow < NN) {
                float v = ob[row * 132 + col] + bias_s[col];
                out[(size_t)grow * DD + col] = gelu_exact(v);
            }
        }
    }
}

// ---------------------------------------------------------------------------
extern "C" void kernel_launch(void* const* d_in, const int* in_sizes, int n_in,
                              void* d_out, int out_size) {
    const float* features = (const float*)d_in[0];
    const int*   src      = (const int*)d_in[1];
    const int*   dst      = (const int*)d_in[2];
    const float* gamma    = (const float*)d_in[3];
    const float* beta     = (const float*)d_in[4];
    const float* W_self   = (const float*)d_in[5];
    const float* W_neigh  = (const float*)d_in[6];
    const float* b        = (const float*)d_in[7];
    float* out = (float*)d_out;

    cudaFuncSetAttribute(k_gemm_mma, cudaFuncAttributeMaxDynamicSharedMemorySize, SM_TOT);

    k_prep<<<391, 256>>>();
    k_count<<<(NE + 255) / 256, 256>>>(dst);
    k_stats<<<512, 128>>>(features);
    k_scan1<<<NBLK, 1024>>>();
    k_scan2<<<1, 128>>>();
    k_scan3<<<(NN + 255) / 256, 256>>>();
    k_norm<<<1024, 128>>>(features, gamma, beta);
    k_scatter<<<(NE + 255) / 256, 256>>>(src, dst);
    k_gather<<<(NN * 32 + 255) / 256, 256>>>();
    k_gemm_mma<<<148, 256, SM_TOT>>>(W_self, W_neigh, b, out);
}

// round 7
// speedup vs baseline: 2.4379x; 1.5638x over previous
#include <cuda_runtime.h>
#include <cuda_bf16.h>
#include <math.h>
#include <stdint.h>

#define NN 100000
#define DD 128
#define NE 800000
#define KK 256
#define BMT 64
#define NTILES ((NN + BMT - 1) / BMT)   // 1563
#define KPAD 264
#define NBLK 98                         // ceil(NN/1024)
#define GEMM_GRID 148

// ---------------------------------------------------------------------------
__device__ float g_h[NN * DD];
__device__ float g_agg[NN * DD];
__device__ float g_sum[DD];
__device__ float g_sumsq[DD];
__device__ int   g_cnt[NN];
__device__ int   g_ptr[NN + 1];
__device__ int   g_cur[NN];
__device__ int   g_csrc[NE];
__device__ int   g_bsum[NBLK];

// ---------------------------------------------------------------------------
__device__ __forceinline__ uint32_t smem_to_u32(const void* p) {
    uint32_t a;
    asm("{ .reg .u64 t; cvta.to.shared.u64 t, %1; cvt.u32.u64 %0, t; }"
        : "=r"(a) : "l"(p));
    return a;
}
#define LDSM_X4(r, addr) \
    asm volatile("ldmatrix.sync.aligned.m8n8.x4.shared.b16 {%0,%1,%2,%3}, [%4];" \
        : "=r"((r)[0]), "=r"((r)[1]), "=r"((r)[2]), "=r"((r)[3]) : "r"(addr))
#define MMA16816(c, a, b0, b1) \
    asm volatile("mma.sync.aligned.m16n8k16.row.col.f32.bf16.bf16.f32 " \
        "{%0,%1,%2,%3}, {%4,%5,%6,%7}, {%8,%9}, {%0,%1,%2,%3};" \
        : "+f"((c)[0]), "+f"((c)[1]), "+f"((c)[2]), "+f"((c)[3]) \
        : "r"((a)[0]), "r"((a)[1]), "r"((a)[2]), "r"((a)[3]), "r"(b0), "r"(b1))

// ---------------------------------------------------------------------------
__global__ void k_prep() {
    int i = blockIdx.x * blockDim.x + threadIdx.x;
    int stride = gridDim.x * blockDim.x;
    for (int j = i; j < NN; j += stride) g_cnt[j] = 0;
    if (i < DD) { g_sum[i] = 0.f; g_sumsq[i] = 0.f; }
}

// fused: blocks [0,512) do column stats; blocks [512, 512+3125) do degree count
__global__ void k_count_stats(const float* __restrict__ feat,
                              const int* __restrict__ dst) {
    int tid = threadIdx.x;
    if (blockIdx.x < 512) {
        int d = tid & 127;
        int half = tid >> 7;
        float s = 0.f, s2 = 0.f;
        for (int r = blockIdx.x * 2 + half; r < NN; r += 1024) {
            float v = feat[r * DD + d];
            s += v; s2 += v * v;
        }
        atomicAdd(&g_sum[d], s);
        atomicAdd(&g_sumsq[d], s2);
    } else {
        int i = (blockIdx.x - 512) * 256 + tid;
        if (i < NE) atomicAdd(&g_cnt[dst[i]], 1);
    }
}

// ---- 2-level exclusive scan over g_cnt -> g_ptr --------------------------
__global__ void k_scan1() {
    __shared__ int s[1024];
    int tid = threadIdx.x;
    int i = blockIdx.x * 1024 + tid;
    int v = (i < NN) ? g_cnt[i] : 0;
    s[tid] = v;
    __syncthreads();
#pragma unroll
    for (int off = 1; off < 1024; off <<= 1) {
        int t = (tid >= off) ? s[tid - off] : 0;
        __syncthreads();
        s[tid] += t;
        __syncthreads();
    }
    if (i < NN) g_ptr[i] = s[tid] - v;
    if (tid == 1023) g_bsum[blockIdx.x] = s[1023];
}
__global__ void k_scan2() {
    __shared__ int s[128];
    int tid = threadIdx.x;
    int v = (tid < NBLK) ? g_bsum[tid] : 0;
    s[tid] = v;
    __syncthreads();
#pragma unroll
    for (int off = 1; off < 128; off <<= 1) {
        int t = (tid >= off) ? s[tid - off] : 0;
        __syncthreads();
        s[tid] += t;
        __syncthreads();
    }
    if (tid < NBLK) g_bsum[tid] = s[tid] - v;
}
__global__ void k_scan3() {
    int i = blockIdx.x * blockDim.x + threadIdx.x;
    if (i < NN) {
        int p = g_ptr[i] + g_bsum[i >> 10];
        g_ptr[i] = p;
        g_cur[i] = p;
    }
    if (i == 0) g_ptr[NN] = NE;
}
__global__ void k_scatter(const int* __restrict__ src, const int* __restrict__ dst) {
    int i = blockIdx.x * blockDim.x + threadIdx.x;
    if (i < NE) {
        int pos = atomicAdd(&g_cur[dst[i]], 1);
        g_csrc[pos] = src[i];
    }
}

// ---------------------------------------------------------------------------
__global__ void k_norm(const float* __restrict__ feat,
                       const float* __restrict__ gamma,
                       const float* __restrict__ beta) {
    int d = threadIdx.x;
    const float invN = 1.f / (float)NN;
    float mean = g_sum[d] * invN;
    float var  = fmaxf(g_sumsq[d] * invN - mean * mean, 0.f);
    float isg  = rsqrtf(var + 1e-5f) * gamma[d];
    float be   = beta[d];
    for (int r = blockIdx.x; r < NN; r += gridDim.x)
        g_h[r * DD + d] = (feat[r * DD + d] - mean) * isg + be;
}

// ---------------------------------------------------------------------------
// gather-aggregate: one warp per dst node, unrolled x2 for MLP
__global__ void k_gather() {
    int gw = (blockIdx.x * blockDim.x + threadIdx.x) >> 5;
    int lane = threadIdx.x & 31;
    if (gw >= NN) return;
    int beg = g_ptr[gw];
    int end = g_ptr[gw + 1];
    float4 a0 = make_float4(0.f, 0.f, 0.f, 0.f);
    float4 a1 = make_float4(0.f, 0.f, 0.f, 0.f);
    int e = beg;
    for (; e + 2 <= end; e += 2) {
        int s0 = g_csrc[e];
        int s1 = g_csrc[e + 1];
        float4 v0 = reinterpret_cast<const float4*>(g_h + (size_t)s0 * DD)[lane];
        float4 v1 = reinterpret_cast<const float4*>(g_h + (size_t)s1 * DD)[lane];
        a0.x += v0.x; a0.y += v0.y; a0.z += v0.z; a0.w += v0.w;
        a1.x += v1.x; a1.y += v1.y; a1.z += v1.z; a1.w += v1.w;
    }
    if (e < end) {
        int s0 = g_csrc[e];
        float4 v0 = reinterpret_cast<const float4*>(g_h + (size_t)s0 * DD)[lane];
        a0.x += v0.x; a0.y += v0.y; a0.z += v0.z; a0.w += v0.w;
    }
    float iv = 1.f / fmaxf((float)(end - beg), 1.f);
    reinterpret_cast<float4*>(g_agg + (size_t)gw * DD)[lane] =
        make_float4((a0.x + a1.x) * iv, (a0.y + a1.y) * iv,
                    (a0.z + a1.z) * iv, (a0.w + a1.w) * iv);
}

// ---------------------------------------------------------------------------
// bf16x3 mma.sync GEMM with register-prefetch pipeline + direct-STG epilogue.
__device__ __forceinline__ float gelu_exact(float x) {
    return 0.5f * x * (1.f + erff(x * 0.70710678118654752f));
}
__device__ __forceinline__ uint32_t pack_bf16x2(__nv_bfloat16 lo, __nv_bfloat16 hi) {
    __nv_bfloat162 p(lo, hi);
    return *reinterpret_cast<uint32_t*>(&p);
}

#define SM_BHI  0
#define SM_BLO  (SM_BHI + DD * KPAD * 2)
#define SM_A    (SM_BLO + DD * KPAD * 2)
#define SM_ALO  (SM_A + BMT * KPAD * 2)
#define SM_BIAS (SM_ALO + BMT * KPAD * 2)
#define SM_TOT  (SM_BIAS + 512)

__global__ void __launch_bounds__(256, 1)
k_gemm_mma(const float* __restrict__ Wself,
           const float* __restrict__ Wneigh,
           const float* __restrict__ bias,
           float* __restrict__ out) {
    extern __shared__ char smem[];
    const uint32_t smem_base = smem_to_u32(smem);
    const int tid  = threadIdx.x;
    const int wid  = tid >> 5;
    const int lane = tid & 31;

    // ---- stage B once: transpose, +I fold, bf16 hi/lo split
    for (int i = 0; i < 32; i++) {
        int e = tid + i * 256;
        int k = e >> 5;
        int c4 = e & 31;
        const float4* wr = (k < DD)
            ? reinterpret_cast<const float4*>(Wself  + (size_t)k * DD)
            : reinterpret_cast<const float4*>(Wneigh + (size_t)(k - DD) * DD);
        float4 w = wr[c4];
        float wv[4] = {w.x, w.y, w.z, w.w};
#pragma unroll
        for (int j = 0; j < 4; j++) {
            int n = c4 * 4 + j;
            float v = wv[j] + ((k < DD && n == k) ? 1.0f : 0.0f);
            __nv_bfloat16 hi = __float2bfloat16(v);
            __nv_bfloat16 lo = __float2bfloat16(v - __bfloat162float(hi));
            uint32_t off = ((uint32_t)n * KPAD + (uint32_t)k) * 2u;
            *reinterpret_cast<__nv_bfloat16*>(smem + SM_BHI + off) = hi;
            *reinterpret_cast<__nv_bfloat16*>(smem + SM_BLO + off) = lo;
        }
    }
    if (tid < DD) *reinterpret_cast<float*>(smem + SM_BIAS + tid * 4) = bias[tid];

    const float* bias_s = reinterpret_cast<const float*>(smem + SM_BIAS);
    const int wr2 = wid >> 2;
    const int wc  = wid & 3;
    const int a_row_l = lane & 15;
    const int a_k_l   = (lane >> 4) << 3;
    const int b_n_l   = ((lane >> 4) << 3) + (lane & 7);
    const int b_k_l   = ((lane >> 3) & 1) << 3;

    // per-thread A staging coordinates (16 float4s: row = tid>>2 + 64*i? no:)
    // e = tid + i*256: r = e>>6 (0..63), c4 = e&63  (k = c4*4)
    float4 v[16];

    int tile = blockIdx.x;
    if (tile < NTILES) {
        const int row0 = tile * BMT;
#pragma unroll
        for (int i = 0; i < 16; i++) {
            int e = tid + i * 256;
            int r  = e >> 6;
            int c4 = e & 63;
            int gr = min(row0 + r, NN - 1);
            v[i] = (c4 < 32)
                ? reinterpret_cast<const float4*>(g_h   + (size_t)gr * DD)[c4]
                : reinterpret_cast<const float4*>(g_agg + (size_t)gr * DD)[c4 - 32];
        }
    }
    __syncthreads();   // B ready

    for (; tile < NTILES; tile += GEMM_GRID) {
        const int row0 = tile * BMT;

        // ---- convert prefetched regs -> smem A planes
#pragma unroll
        for (int i = 0; i < 16; i++) {
            int e = tid + i * 256;
            int r  = e >> 6;
            int c4 = e & 63;
            float x[4] = {v[i].x, v[i].y, v[i].z, v[i].w};
            __nv_bfloat16 h[4], l[4];
#pragma unroll
            for (int j = 0; j < 4; j++) {
                h[j] = __float2bfloat16(x[j]);
                l[j] = __float2bfloat16(x[j] - __bfloat162float(h[j]));
            }
            uint32_t boff = ((uint32_t)r * KPAD + (uint32_t)c4 * 4) * 2u;
            *reinterpret_cast<uint2*>(smem + SM_A + boff) =
                make_uint2(pack_bf16x2(h[0], h[1]), pack_bf16x2(h[2], h[3]));
            *reinterpret_cast<uint2*>(smem + SM_ALO + boff) =
                make_uint2(pack_bf16x2(l[0], l[1]), pack_bf16x2(l[2], l[3]));
        }
        __syncthreads();

        // ---- issue next tile's loads (landing during the k-loop)
        {
            int nxt = tile + GEMM_GRID;
            if (nxt < NTILES) {
                const int nrow0 = nxt * BMT;
#pragma unroll
                for (int i = 0; i < 16; i++) {
                    int e = tid + i * 256;
                    int r  = e >> 6;
                    int c4 = e & 63;
                    int gr = min(nrow0 + r, NN - 1);
                    v[i] = (c4 < 32)
                        ? reinterpret_cast<const float4*>(g_h   + (size_t)gr * DD)[c4]
                        : reinterpret_cast<const float4*>(g_agg + (size_t)gr * DD)[c4 - 32];
                }
            }
        }

        float c[2][4][4];
#pragma unroll
        for (int mt = 0; mt < 2; mt++)
#pragma unroll
            for (int nt = 0; nt < 4; nt++)
#pragma unroll
                for (int q = 0; q < 4; q++) c[mt][nt][q] = 0.f;

#pragma unroll 4
        for (int ks = 0; ks < 16; ks++) {
            const int k0 = ks * 16;
            uint32_t a_hi[2][4], a_lo[2][4], b_hi[2][4], b_lo[2][4];
#pragma unroll
            for (int mt = 0; mt < 2; mt++) {
                uint32_t ao = (uint32_t)((wr2 * 32 + mt * 16 + a_row_l) * KPAD
                                         + k0 + a_k_l) * 2u;
                LDSM_X4(a_hi[mt], smem_base + SM_A + ao);
                LDSM_X4(a_lo[mt], smem_base + SM_ALO + ao);
            }
#pragma unroll
            for (int g = 0; g < 2; g++) {
                uint32_t bo = (uint32_t)((wc * 32 + g * 16 + b_n_l) * KPAD
                                         + k0 + b_k_l) * 2u;
                LDSM_X4(b_hi[g], smem_base + SM_BHI + bo);
                LDSM_X4(b_lo[g], smem_base + SM_BLO + bo);
            }
            // pass-major order: 8-deep independence between same-acc MMAs
#pragma unroll
            for (int mt = 0; mt < 2; mt++)
#pragma unroll
                for (int nt = 0; nt < 4; nt++) {
                    int g = nt >> 1, s = (nt & 1) * 2;
                    MMA16816(c[mt][nt], a_hi[mt], b_hi[g][s], b_hi[g][s + 1]);
                }
#pragma unroll
            for (int mt = 0; mt < 2; mt++)
#pragma unroll
                for (int nt = 0; nt < 4; nt++) {
                    int g = nt >> 1, s = (nt & 1) * 2;
                    MMA16816(c[mt][nt], a_hi[mt], b_lo[g][s], b_lo[g][s + 1]);
                }
#pragma unroll
            for (int mt = 0; mt < 2; mt++)
#pragma unroll
                for (int nt = 0; nt < 4; nt++) {
                    int g = nt >> 1, s = (nt & 1) * 2;
                    MMA16816(c[mt][nt], a_lo[mt], b_hi[g][s], b_hi[g][s + 1]);
                }
        }

        // ---- epilogue: bias + exact GELU + direct fragment stores
#pragma unroll
        for (int mt = 0; mt < 2; mt++) {
            int rbase = row0 + wr2 * 32 + mt * 16 + (lane >> 2);
#pragma unroll
            for (int nt = 0; nt < 4; nt++) {
                int col = wc * 32 + nt * 8 + 2 * (lane & 3);
                float b0 = bias_s[col], b1 = bias_s[col + 1];
                if (rbase < NN) {
                    float2 o = make_float2(gelu_exact(c[mt][nt][0] + b0),
                                           gelu_exact(c[mt][nt][1] + b1));
                    *reinterpret_cast<float2*>(out + (size_t)rbase * DD + col) = o;
                }
                if (rbase + 8 < NN) {
                    float2 o = make_float2(gelu_exact(c[mt][nt][2] + b0),
                                           gelu_exact(c[mt][nt][3] + b1));
                    *reinterpret_cast<float2*>(out + (size_t)(rbase + 8) * DD + col) = o;
                }
            }
        }
        __syncthreads();   // A smem consumed by all warps before next overwrite
    }
}

// ---------------------------------------------------------------------------
extern "C" void kernel_launch(void* const* d_in, const int* in_sizes, int n_in,
                              void* d_out, int out_size) {
    const float* features = (const float*)d_in[0];
    const int*   src      = (const int*)d_in[1];
    const int*   dst      = (const int*)d_in[2];
    const float* gamma    = (const float*)d_in[3];
    const float* beta     = (const float*)d_in[4];
    const float* W_self   = (const float*)d_in[5];
    const float* W_neigh  = (const float*)d_in[6];
    const float* b        = (const float*)d_in[7];
    float* out = (float*)d_out;

    cudaFuncSetAttribute(k_gemm_mma, cudaFuncAttributeMaxDynamicSharedMemorySize, SM_TOT);

    k_prep<<<391, 256>>>();
    k_count_stats<<<512 + (NE + 255) / 256, 256>>>(features, dst);
    k_scan1<<<NBLK, 1024>>>();
    k_scan2<<<1, 128>>>();
    k_scan3<<<(NN + 255) / 256, 256>>>();
    k_norm<<<1024, 128>>>(features, gamma, beta);
    k_scatter<<<(NE + 255) / 256, 256>>>(src, dst);
    k_gather<<<(NN * 32 + 255) / 256, 256>>>();
    k_gemm_mma<<<GEMM_GRID, 256, SM_TOT>>>(W_self, W_neigh, b, out);
}